// round 15
// baseline (speedup 1.0000x reference)
#include <cuda_runtime.h>
#include <cuda_bf16.h>
#include <stdint.h>
#include <math.h>

// Problem constants
#define CIN   256
#define COUT  128
#define KK    9
#define HIN   64
#define WIN   64
#define XP    65          // padded x dims (extra zero row/col)
#define HH    128
#define WW    128
#define NB    2
#define KTOT  (KK * COUT)        // 1152
#define STAGES (KTOT / 32)       // 36

// ---------------- device scratch (no allocations allowed) ----------------
__device__ __align__(16) float g_upcl[NB * HH * WW * COUT]; // up fp32, channel-last (16MB)
__device__ int   g_sy[NB][KK], g_sx[NB][KK];
__device__ float g_cw[NB][KK][4];
__device__ __align__(16) __nv_bfloat16 g_Whi[CIN * KTOT];   // deform W [o][kk*128+ci]
__device__ __align__(16) __nv_bfloat16 g_Wlo[CIN * KTOT];
__device__ __align__(16) __nv_bfloat16 g_Shi[NB * HH * WW * KTOT]; // 75.5MB
__device__ __align__(16) __nv_bfloat16 g_Slo[NB * HH * WW * KTOT]; // 75.5MB
__device__ __align__(16) __nv_bfloat16 g_xpad_hi[NB * XP * XP * CIN]; // 4.3MB
__device__ __align__(16) __nv_bfloat16 g_xpad_lo[NB * XP * XP * CIN];
__device__ __align__(16) __nv_bfloat16 g_Wch[COUT * 2304];  // tconv class weights
__device__ __align__(16) __nv_bfloat16 g_Wcl[COUT * 2304];

__constant__ int c_clsBase[4] = {0, 256, 768, 1280};
__constant__ int c_clsK[4]    = {256, 512, 512, 1024};

// ---------------- PTX helpers (target-independent, sm_80+) ----------------
__device__ __forceinline__ uint32_t s2u(const void* p) {
    uint32_t a;
    asm("{ .reg .u64 t; cvta.to.shared.u64 t, %1; cvt.u32.u64 %0, t; }" : "=r"(a) : "l"(p));
    return a;
}
__device__ __forceinline__ void cp16(uint32_t d, const void* s) {
    asm volatile("cp.async.cg.shared.global [%0], [%1], 16;" :: "r"(d), "l"(s));
}
__device__ __forceinline__ void cp_commit() {
    asm volatile("cp.async.commit_group;" ::: "memory");
}
__device__ __forceinline__ void cp_wait_all() {
    asm volatile("cp.async.wait_group 0;" ::: "memory");
}
__device__ __forceinline__ void cp_wait_1() {
    asm volatile("cp.async.wait_group 1;" ::: "memory");
}
__device__ __forceinline__ void ldsm4(uint32_t* r, uint32_t a) {
    asm volatile("ldmatrix.sync.aligned.m8n8.x4.shared.b16 {%0,%1,%2,%3}, [%4];"
                 : "=r"(r[0]), "=r"(r[1]), "=r"(r[2]), "=r"(r[3]) : "r"(a));
}
__device__ __forceinline__ void ldsm2(uint32_t* r, uint32_t a) {
    asm volatile("ldmatrix.sync.aligned.m8n8.x2.shared.b16 {%0,%1}, [%2];"
                 : "=r"(r[0]), "=r"(r[1]) : "r"(a));
}
__device__ __forceinline__ void mma_bf16(float* d, const uint32_t* a, const uint32_t* b) {
    asm volatile(
        "mma.sync.aligned.m16n8k16.row.col.f32.bf16.bf16.f32 "
        "{%0,%1,%2,%3}, {%4,%5,%6,%7}, {%8,%9}, {%0,%1,%2,%3};"
        : "+f"(d[0]), "+f"(d[1]), "+f"(d[2]), "+f"(d[3])
        : "r"(a[0]), "r"(a[1]), "r"(a[2]), "r"(a[3]), "r"(b[0]), "r"(b[1]));
}

union BFP { __nv_bfloat16 b[4]; uint2 v; };

// ---------------------------------------------------------------------------
// Kernel 1: fused weight preprocessing (deform split + tconv class weights)
// ---------------------------------------------------------------------------
__global__ void wprep_kernel(const float* __restrict__ tw) {
    int i = blockIdx.x * blockDim.x + threadIdx.x;
    if (i >= CIN * KTOT) return;
    {   // deform split
        int o = i / KTOT, kidx = i % KTOT;
        int kk = kidx >> 7, ci = kidx & 127;
        float w = tw[(o * COUT + ci) * KK + kk];
        __nv_bfloat16 h = __float2bfloat16(w);
        g_Whi[i] = h;
        g_Wlo[i] = __float2bfloat16(w - __bfloat162float(h));
    }
    {   // tconv class weights
        int co = i / 2304, kf = i % 2304;
        int cls = (kf >= 1280) ? 3 : (kf >= 768) ? 2 : (kf >= 256) ? 1 : 0;
        int k = kf - c_clsBase[cls];
        int py = cls >> 1, pxp = cls & 1;
        int nkx = pxp ? 2 : 1;
        int tap = k >> 8, ci = k & 255;
        int a = tap / nkx, b = tap % nkx;
        int ky = py ? (a ? 2 : 0) : 1;
        int kx = pxp ? (b ? 2 : 0) : 1;
        float w = tw[(ci * COUT + co) * KK + (2 - ky) * 3 + (2 - kx)];
        __nv_bfloat16 h = __float2bfloat16(w);
        g_Wch[i] = h;
        g_Wcl[i] = __float2bfloat16(w - __bfloat162float(h));
    }
}

// ---------------------------------------------------------------------------
// Kernel 2: x -> channel-last bf16 hi/lo with zero pad row/col 64.
// ---------------------------------------------------------------------------
__global__ void __launch_bounds__(256)
xsplit_kernel(const float* __restrict__ x) {
    const int y0 = blockIdx.x, n = blockIdx.y;
    const int tid = threadIdx.x;
    __nv_bfloat16* oh = g_xpad_hi + (size_t)(n * XP + y0) * XP * CIN;
    __nv_bfloat16* ol = g_xpad_lo + (size_t)(n * XP + y0) * XP * CIN;

    if (y0 == 64) {
        for (int idx = tid; idx < XP * CIN / 8; idx += 256) {
            *(uint4*)(oh + idx * 8) = make_uint4(0, 0, 0, 0);
            *(uint4*)(ol + idx * 8) = make_uint4(0, 0, 0, 0);
        }
        return;
    }
    __shared__ float tile[64][65];
    for (int cc = 0; cc < 4; cc++) {
        #pragma unroll
        for (int r = 0; r < 16; r++) {
            int ci = (tid >> 6) + r * 4;
            int x0 = tid & 63;
            tile[ci][x0] = x[((size_t)(n * CIN + cc * 64 + ci) * HIN + y0) * WIN + x0];
        }
        __syncthreads();
        #pragma unroll
        for (int r = 0; r < 16; r++) {
            int x0 = (tid >> 6) + r * 4;
            int ci = tid & 63;
            float v = tile[ci][x0];
            __nv_bfloat16 h = __float2bfloat16(v);
            oh[x0 * CIN + cc * 64 + ci] = h;
            ol[x0 * CIN + cc * 64 + ci] = __float2bfloat16(v - __bfloat162float(h));
        }
        __syncthreads();
    }
    if (tid < CIN) {
        oh[64 * CIN + tid] = __float2bfloat16(0.f);
        ol[64 * CIN + tid] = __float2bfloat16(0.f);
    }
}

// ---------------------------------------------------------------------------
// Kernel 3: offset branch, warp-parallel
// ---------------------------------------------------------------------------
__global__ void __launch_bounds__(1024)
offsets_kernel(const float* __restrict__ lat,
               const float* __restrict__ w1,
               const float* __restrict__ b1,
               const float* __restrict__ w2,
               const float* __restrict__ b2) {
    __shared__ float h[NB][64];
    __shared__ float oc[NB][18];
    const int tid = threadIdx.x, lane = tid & 31, w = tid >> 5;

    #pragma unroll
    for (int t = 0; t < 4; t++) {
        int o = w * 4 + t;
        int n = o >> 6, j = o & 63;
        float s = 0.f;
        #pragma unroll
        for (int r = 0; r < 4; r++) {
            int i = lane + r * 32;
            s += lat[n * COUT + i] * w1[(j * COUT + i) * KK + 4];
        }
        #pragma unroll
        for (int d = 16; d; d >>= 1) s += __shfl_xor_sync(0xffffffffu, s, d);
        if (lane == 0) h[n][j] = fmaxf(s + b1[j], 0.f);
    }
    __syncthreads();

    for (int o = w; o < NB * 18; o += 32) {
        int n = o / 18, c = o % 18;
        float s = 0.f;
        #pragma unroll
        for (int r = 0; r < 2; r++) {
            int k = lane + r * 32;
            s += h[n][k] * w2[(c * 64 + k) * KK + 4];
        }
        #pragma unroll
        for (int d = 16; d; d >>= 1) s += __shfl_xor_sync(0xffffffffu, s, d);
        if (lane == 0) oc[n][c] = tanhf(s + b2[c]);
    }
    __syncthreads();

    if (tid < NB * KK) {
        int n = tid / KK, kk = tid % KK;
        float oy = oc[n][2 * kk], ox = oc[n][2 * kk + 1];
        float fy = floorf(oy), fx = floorf(ox);
        float dy = oy - fy,  dx = ox - fx;
        g_sy[n][kk] = (kk / 3 - 1) + (int)fy;
        g_sx[n][kk] = (kk % 3 - 1) + (int)fx;
        g_cw[n][kk][0] = (1.f - dy) * (1.f - dx);
        g_cw[n][kk][1] = (1.f - dy) * dx;
        g_cw[n][kk][2] = dy * (1.f - dx);
        g_cw[n][kk][3] = dy * dx;
    }
}

// ---------------------------------------------------------------------------
// Kernel 4: transposed conv as per-parity-class HMMA GEMM, Y-merged:
// one CTA computes rows Ya=bx and Yb=bx+64 (same parity class, same A).
// CTA: M=128 co x N=128 (64 px x 2 rows), K = c_clsK[cls].
// smem/stage: Ah 10240 | Al 10240 | Bh 10240 | Bl 10240 = 40960; x2 buffers.
// ---------------------------------------------------------------------------
__global__ void __launch_bounds__(256)
tconv_gemm_kernel() {
    extern __shared__ __align__(16) unsigned char smraw[];
    const int bx  = blockIdx.x;          // 0..63
    const int pxp = blockIdx.y;
    const int n   = blockIdx.z;
    const int Ya  = bx, Yb = bx + 64;    // same parity
    const int tid = threadIdx.x;
    const int lane = tid & 31, warp = tid >> 5;
    const int wm = warp & 1, wn = warp >> 1;   // M: 2x64, N: 4x32

    const int py  = Ya & 1;
    const int cls = py * 2 + pxp;
    const int Kc  = c_clsK[cls];
    const int kbase = c_clsBase[cls];
    const int nkx = pxp ? 2 : 1;
    const int stages = Kc >> 5;
    const int y0b = Ya >> 1;             // Yb base = y0b + 32
    const uint32_t smb = s2u(smraw);

    const __nv_bfloat16* Ah_src = g_Wch;
    const __nv_bfloat16* Al_src = g_Wcl;
    const __nv_bfloat16* Bh_src = g_xpad_hi + (size_t)n * XP * XP * CIN;
    const __nv_bfloat16* Bl_src = g_xpad_lo + (size_t)n * XP * XP * CIN;

    float acc[4][4][4];
    #pragma unroll
    for (int i = 0; i < 4; i++)
        #pragma unroll
        for (int j = 0; j < 4; j++)
            #pragma unroll
            for (int e = 0; e < 4; e++) acc[i][j][e] = 0.f;

    auto issue = [&](int s, int buf) {
        const int k0 = s * 32;
        const int tap = k0 >> 8;
        const int a = tap / nkx, b = tap % nkx;
        const int dyk = py ? a : 0;
        const int d  = pxp ? b : 0;
        const int cib = k0 & 255;
        #pragma unroll
        for (int j = 0; j < 8; j++) {
            int id = tid + j * 256;            // 0..2047
            uint32_t base = smb + buf * 40960;
            if (id < 1024) {                   // A tiles: 2 x (128 rows x 4 chunks)
                int t = id >> 9;
                int rid = id & 511;
                int r = rid >> 2, c = rid & 3;
                uint32_t dst = base + t * 10240 + r * 80 + c * 16;
                const __nv_bfloat16* src = (t ? Al_src : Ah_src)
                    + (size_t)r * 2304 + kbase + k0 + c * 8;
                cp16(dst, src);
            } else {                           // B tiles: 2 x (128 rows x 4 chunks)
                int rid = id - 1024;           // 0..1023
                int t = rid >> 9;
                int rr = rid & 511;
                int r = rr >> 2, c = rr & 3;   // r = 0..127
                int half = r >> 6, pr = r & 63;
                int yy = y0b + dyk + half * 32;
                uint32_t dst = base + 20480 + t * 10240 + r * 80 + c * 16;
                const __nv_bfloat16* src = (t ? Bl_src : Bh_src)
                    + (size_t)yy * XP * CIN + (size_t)(pr + d) * CIN + cib + c * 8;
                cp16(dst, src);
            }
        }
        cp_commit();
    };

    issue(0, 0);

    for (int s = 0; s < stages; s++) {
        cp_wait_all();
        __syncthreads();
        if (s + 1 < stages) issue(s + 1, (s + 1) & 1);

        const int buf = s & 1;
        const uint32_t Ab = smb + buf * 40960;
        const uint32_t Bb = Ab + 20480;

        #pragma unroll
        for (int ks = 0; ks < 2; ks++) {
            uint32_t afr[2][4][4];
            #pragma unroll
            for (int t = 0; t < 2; t++)
                #pragma unroll
                for (int mt = 0; mt < 4; mt++) {
                    uint32_t ad = Ab + t * 10240 +
                        (wm * 64 + mt * 16 + (lane & 15)) * 80 + ks * 32 + (lane >> 4) * 16;
                    ldsm4(afr[t][mt], ad);
                }
            uint32_t bfr[2][4][2];
            #pragma unroll
            for (int t = 0; t < 2; t++)
                #pragma unroll
                for (int nt = 0; nt < 4; nt++) {
                    uint32_t bd = Bb + t * 10240 +
                        (wn * 32 + nt * 8 + (lane & 7)) * 80 + ks * 32 + ((lane >> 3) & 1) * 16;
                    ldsm2(bfr[t][nt], bd);
                }
            #pragma unroll
            for (int mt = 0; mt < 4; mt++)
                #pragma unroll
                for (int nt = 0; nt < 4; nt++) {
                    mma_bf16(acc[mt][nt], afr[0][mt], bfr[0][nt]);   // hi*hi
                    mma_bf16(acc[mt][nt], afr[0][mt], bfr[1][nt]);   // hi*lo
                    mma_bf16(acc[mt][nt], afr[1][mt], bfr[0][nt]);   // lo*hi
                }
        }
        __syncthreads();
    }

    // epilogue: column q<64 -> row Ya, q>=64 -> row Yb; X = 2*(q&63)+pxp
    float* upn = g_upcl + (size_t)n * HH * WW * COUT;
    #pragma unroll
    for (int mt = 0; mt < 4; mt++) {
        int m0 = wm * 64 + mt * 16 + (lane >> 2);
        #pragma unroll
        for (int nt = 0; nt < 4; nt++) {
            int q = wn * 32 + nt * 8 + (lane & 3) * 2;
            int Yr = (q < 64) ? Ya : Yb;
            int p0 = q & 63;
            float* row = upn + (size_t)Yr * WW * COUT;
            row[(size_t)(2 * p0 + pxp) * COUT + m0]           = acc[mt][nt][0];
            row[(size_t)(2 * (p0 + 1) + pxp) * COUT + m0]     = acc[mt][nt][1];
            row[(size_t)(2 * p0 + pxp) * COUT + m0 + 8]       = acc[mt][nt][2];
            row[(size_t)(2 * (p0 + 1) + pxp) * COUT + m0 + 8] = acc[mt][nt][3];
        }
    }
}

// ---------------------------------------------------------------------------
// Kernel 5: bilinear sampler -> S[n][px][kk*128+ci] bf16 hi/lo.
// 512 threads; 8 items/thread processed in pairs for MLP=8.
// ---------------------------------------------------------------------------
__global__ void __launch_bounds__(512)
sample_kernel() {
    const int kk = blockIdx.x, y = blockIdx.y, n = blockIdx.z;
    const int tid = threadIdx.x;
    const int cg = tid & 31, pxb = tid >> 5;     // cg: ci group of 4; pxb: 0..15
    const int sy = g_sy[n][kk], sx = g_sx[n][kk];
    const float c00 = g_cw[n][kk][0], c01 = g_cw[n][kk][1];
    const float c10 = g_cw[n][kk][2], c11 = g_cw[n][kk][3];
    const int yrow = y + sy;
    const bool yA = (unsigned)yrow < HH, yB = (unsigned)(yrow + 1) < HH;
    const int ci0 = cg * 4;
    const float* rbase = g_upcl + (size_t)n * HH * WW * COUT
                       + (size_t)yrow * WW * COUT + ci0;
    const size_t sobase = ((size_t)((n * HH + y) * WW)) * KTOT + kk * COUT + ci0;
    const float4 z = make_float4(0.f, 0.f, 0.f, 0.f);

    #pragma unroll
    for (int k = 0; k < 8; k += 2) {
        const int pA = pxb + k * 16;
        const int pB = pxb + (k + 1) * 16;
        float4 a00, a01, a10, a11, b00, b01, b10, b11;
        {
            int x0 = pA + sx;
            bool xi = (unsigned)x0 < WW, xj = (unsigned)(x0 + 1) < WW;
            const float* p = rbase + (size_t)x0 * COUT;
            a00 = (yA & xi) ? *(const float4*)p : z;
            a01 = (yA & xj) ? *(const float4*)(p + COUT) : z;
            a10 = (yB & xi) ? *(const float4*)(p + WW * COUT) : z;
            a11 = (yB & xj) ? *(const float4*)(p + WW * COUT + COUT) : z;
        }
        {
            int x0 = pB + sx;
            bool xi = (unsigned)x0 < WW, xj = (unsigned)(x0 + 1) < WW;
            const float* p = rbase + (size_t)x0 * COUT;
            b00 = (yA & xi) ? *(const float4*)p : z;
            b01 = (yA & xj) ? *(const float4*)(p + COUT) : z;
            b10 = (yB & xi) ? *(const float4*)(p + WW * COUT) : z;
            b11 = (yB & xj) ? *(const float4*)(p + WW * COUT + COUT) : z;
        }
        float va[4], vb[4];
        va[0] = c00 * a00.x + c01 * a01.x + c10 * a10.x + c11 * a11.x;
        va[1] = c00 * a00.y + c01 * a01.y + c10 * a10.y + c11 * a11.y;
        va[2] = c00 * a00.z + c01 * a01.z + c10 * a10.z + c11 * a11.z;
        va[3] = c00 * a00.w + c01 * a01.w + c10 * a10.w + c11 * a11.w;
        vb[0] = c00 * b00.x + c01 * b01.x + c10 * b10.x + c11 * b11.x;
        vb[1] = c00 * b00.y + c01 * b01.y + c10 * b10.y + c11 * b11.y;
        vb[2] = c00 * b00.z + c01 * b01.z + c10 * b10.z + c11 * b11.z;
        vb[3] = c00 * b00.w + c01 * b01.w + c10 * b10.w + c11 * b11.w;
        BFP pha, pla, phb, plb;
        #pragma unroll
        for (int e = 0; e < 4; e++) {
            __nv_bfloat16 ha = __float2bfloat16(va[e]);
            pha.b[e] = ha;
            pla.b[e] = __float2bfloat16(va[e] - __bfloat162float(ha));
            __nv_bfloat16 hb = __float2bfloat16(vb[e]);
            phb.b[e] = hb;
            plb.b[e] = __float2bfloat16(vb[e] - __bfloat162float(hb));
        }
        *(uint2*)(g_Shi + sobase + (size_t)pA * KTOT) = pha.v;
        *(uint2*)(g_Slo + sobase + (size_t)pA * KTOT) = pla.v;
        *(uint2*)(g_Shi + sobase + (size_t)pB * KTOT) = phb.v;
        *(uint2*)(g_Slo + sobase + (size_t)pB * KTOT) = plb.v;
    }
}

// ---------------------------------------------------------------------------
// Kernel 6: deform GEMM, ob-merged: M=256 x N=128 per CTA (16 warps),
// 3-stage cp.async ring. Grid (y=128, n=2). (unchanged from R13)
// ---------------------------------------------------------------------------
__global__ void __launch_bounds__(512, 1)
gemm_kernel(float* __restrict__ out) {
    extern __shared__ __align__(16) unsigned char smraw[];
    const int y   = blockIdx.x;
    const int n   = blockIdx.y;
    const int tid = threadIdx.x;
    const int lane = tid & 31, warp = tid >> 5;
    const int wm = warp & 3, wn = warp >> 2;   // 4x4 warp grid: 64 M x 32 N each

    const uint32_t smb = s2u(smraw);

    const __nv_bfloat16* srcA_h = g_Whi;
    const __nv_bfloat16* srcA_l = g_Wlo;
    const size_t bofs = (size_t)((n * HH + y) * WW) * KTOT;
    const __nv_bfloat16* srcB_h = g_Shi + bofs;
    const __nv_bfloat16* srcB_l = g_Slo + bofs;

    float acc[4][4][4];
    #pragma unroll
    for (int i = 0; i < 4; i++)
        #pragma unroll
        for (int j = 0; j < 4; j++)
            #pragma unroll
            for (int e = 0; e < 4; e++) acc[i][j][e] = 0.f;

    auto issue = [&](int s, int buf) {
        const int k0 = s * 32;
        #pragma unroll
        for (int j = 0; j < 6; j++) {
            int chunk = tid + j * 512;          // 0..3071
            uint32_t base = smb + buf * 61440;
            if (chunk < 2048) {                 // A tiles: 2 x 256 rows x 4 chunks
                int t = chunk >> 10;
                int rid = chunk & 1023;
                int r = rid >> 2, c = rid & 3;
                uint32_t dst = base + t * 20480 + r * 80 + c * 16;
                const __nv_bfloat16* src = (t ? srcA_l : srcA_h) + (size_t)r * KTOT + k0 + c * 8;
                cp16(dst, src);
            } else {                            // B tiles: 2 x 128 rows x 4 chunks
                int rid = chunk - 2048;
                int t = rid >> 9;
                int rr = rid & 511;
                int r = rr >> 2, c = rr & 3;
                uint32_t dst = base + 40960 + t * 10240 + r * 80 + c * 16;
                const __nv_bfloat16* src = (t ? srcB_l : srcB_h) + (size_t)r * KTOT + k0 + c * 8;
                cp16(dst, src);
            }
        }
        cp_commit();
    };

    issue(0, 0);
    issue(1, 1);

    for (int s = 0; s < STAGES; s++) {
        cp_wait_1();            // stage s copy complete (<=1 group pending)
        __syncthreads();        // all warps done with the buffer being refilled
        if (s + 2 < STAGES) issue(s + 2, (s + 2) % 3);

        const int buf = s % 3;
        const uint32_t Ab = smb + buf * 61440;
        const uint32_t Bb = Ab + 40960;

        #pragma unroll
        for (int ks = 0; ks < 2; ks++) {
            uint32_t afr[2][4][4];
            #pragma unroll
            for (int t = 0; t < 2; t++)
                #pragma unroll
                for (int mt = 0; mt < 4; mt++) {
                    uint32_t ad = Ab + t * 20480 +
                        (wm * 64 + mt * 16 + (lane & 15)) * 80 + ks * 32 + (lane >> 4) * 16;
                    ldsm4(afr[t][mt], ad);
                }
            uint32_t bfr[2][4][2];
            #pragma unroll
            for (int t = 0; t < 2; t++)
                #pragma unroll
                for (int nt = 0; nt < 4; nt++) {
                    uint32_t bd = Bb + t * 10240 +
                        (wn * 32 + nt * 8 + (lane & 7)) * 80 + ks * 32 + ((lane >> 3) & 1) * 16;
                    ldsm2(bfr[t][nt], bd);
                }
            #pragma unroll
            for (int mt = 0; mt < 4; mt++)
                #pragma unroll
                for (int nt = 0; nt < 4; nt++) {
                    mma_bf16(acc[mt][nt], afr[0][mt], bfr[0][nt]);
                    mma_bf16(acc[mt][nt], afr[0][mt], bfr[1][nt]);
                    mma_bf16(acc[mt][nt], afr[1][mt], bfr[0][nt]);
                }
        }
    }

    #pragma unroll
    for (int mt = 0; mt < 4; mt++) {
        int m = wm * 64 + mt * 16 + (lane >> 2);
        float* pbase = out + (((size_t)(n * CIN + m) * HH + y) * WW);
        #pragma unroll
        for (int nt = 0; nt < 4; nt++) {
            int xcol = wn * 32 + nt * 8 + (lane & 3) * 2;
            *(float2*)(pbase + xcol) = make_float2(acc[mt][nt][0], acc[mt][nt][1]);
            *(float2*)(pbase + 8 * HH * WW + xcol) = make_float2(acc[mt][nt][2], acc[mt][nt][3]);
        }
    }
}

// ---------------------------------------------------------------------------
extern "C" void kernel_launch(void* const* d_in, const int* in_sizes, int n_in,
                              void* d_out, int out_size) {
    const float* x   = (const float*)d_in[0];
    const float* lat = (const float*)d_in[1];
    const float* tw  = (const float*)d_in[2];
    const float* w1  = (const float*)d_in[3];
    const float* b1  = (const float*)d_in[4];
    const float* w2  = (const float*)d_in[5];
    const float* b2  = (const float*)d_in[6];
    float* out = (float*)d_out;

    cudaFuncSetAttribute(gemm_kernel,
                         cudaFuncAttributeMaxDynamicSharedMemorySize, 184320);
    cudaFuncSetAttribute(tconv_gemm_kernel,
                         cudaFuncAttributeMaxDynamicSharedMemorySize, 81920);

    wprep_kernel<<<(CIN * KTOT + 255) / 256, 256>>>(tw);
    xsplit_kernel<<<dim3(XP, NB), 256>>>(x);
    offsets_kernel<<<1, 1024>>>(lat, w1, b1, w2, b2);
    {
        dim3 grid(64, 2, NB);   // (Y-pair, x-parity, n)
        tconv_gemm_kernel<<<grid, 256, 81920>>>();
    }
    {
        dim3 grid(KK, HH, NB);
        sample_kernel<<<grid, 512>>>();
    }
    {
        dim3 grid(HH, NB);
        gemm_kernel<<<grid, 512, 184320>>>(out);
    }
}

// round 16
// speedup vs baseline: 1.0277x; 1.0277x over previous
#include <cuda_runtime.h>
#include <cuda_bf16.h>
#include <stdint.h>
#include <math.h>

// Problem constants
#define CIN   256
#define COUT  128
#define KK    9
#define HIN   64
#define WIN   64
#define XP    65          // padded x dims (extra zero row/col)
#define HH    128
#define WW    128
#define NB    2
#define KTOT  (KK * COUT)        // 1152
#define STAGES (KTOT / 32)       // 36

// gemm smem layout (per buffer)
#define GBUF   98880
#define SLABO  61440             // slab offset inside buffer
#define SLABR  18720             // slab row (r) stride: 130 px * 144B

// ---------------- device scratch (no allocations allowed) ----------------
__device__ __align__(16) float g_upcl[NB * HH * WW * COUT]; // up fp32, channel-last (16MB)
__device__ int   g_sy[NB][KK], g_sx[NB][KK];
__device__ float g_cw[NB][KK][4];
__device__ __align__(16) __nv_bfloat16 g_Whi[CIN * KTOT];   // deform W [o][kk*128+ci]
__device__ __align__(16) __nv_bfloat16 g_Wlo[CIN * KTOT];
__device__ __align__(16) __nv_bfloat16 g_xpad_hi[NB * XP * XP * CIN]; // 4.3MB
__device__ __align__(16) __nv_bfloat16 g_xpad_lo[NB * XP * XP * CIN];
__device__ __align__(16) __nv_bfloat16 g_Wch[COUT * 2304];  // tconv class weights
__device__ __align__(16) __nv_bfloat16 g_Wcl[COUT * 2304];

__constant__ int c_clsBase[4] = {0, 256, 768, 1280};
__constant__ int c_clsK[4]    = {256, 512, 512, 1024};

// ---------------- PTX helpers (target-independent, sm_80+) ----------------
__device__ __forceinline__ uint32_t s2u(const void* p) {
    uint32_t a;
    asm("{ .reg .u64 t; cvta.to.shared.u64 t, %1; cvt.u32.u64 %0, t; }" : "=r"(a) : "l"(p));
    return a;
}
__device__ __forceinline__ void cp16(uint32_t d, const void* s) {
    asm volatile("cp.async.cg.shared.global [%0], [%1], 16;" :: "r"(d), "l"(s));
}
// zfill variant: copies src_sz bytes (0 or 16), zero-fills the rest of 16B
__device__ __forceinline__ void cp16z(uint32_t d, const void* s, uint32_t src_sz) {
    asm volatile("cp.async.cg.shared.global [%0], [%1], 16, %2;"
                 :: "r"(d), "l"(s), "r"(src_sz));
}
__device__ __forceinline__ void cp_commit() {
    asm volatile("cp.async.commit_group;" ::: "memory");
}
__device__ __forceinline__ void cp_wait_all() {
    asm volatile("cp.async.wait_group 0;" ::: "memory");
}
__device__ __forceinline__ void cp_wait_1() {
    asm volatile("cp.async.wait_group 1;" ::: "memory");
}
__device__ __forceinline__ void ldsm4(uint32_t* r, uint32_t a) {
    asm volatile("ldmatrix.sync.aligned.m8n8.x4.shared.b16 {%0,%1,%2,%3}, [%4];"
                 : "=r"(r[0]), "=r"(r[1]), "=r"(r[2]), "=r"(r[3]) : "r"(a));
}
__device__ __forceinline__ void ldsm2(uint32_t* r, uint32_t a) {
    asm volatile("ldmatrix.sync.aligned.m8n8.x2.shared.b16 {%0,%1}, [%2];"
                 : "=r"(r[0]), "=r"(r[1]) : "r"(a));
}
__device__ __forceinline__ void mma_bf16(float* d, const uint32_t* a, const uint32_t* b) {
    asm volatile(
        "mma.sync.aligned.m16n8k16.row.col.f32.bf16.bf16.f32 "
        "{%0,%1,%2,%3}, {%4,%5,%6,%7}, {%8,%9}, {%0,%1,%2,%3};"
        : "+f"(d[0]), "+f"(d[1]), "+f"(d[2]), "+f"(d[3])
        : "r"(a[0]), "r"(a[1]), "r"(a[2]), "r"(a[3]), "r"(b[0]), "r"(b[1]));
}

union BF8 { __nv_bfloat16 b[8]; uint4 v; };

// ---------------------------------------------------------------------------
// Kernel 1: fused weight preprocessing (deform split + tconv class weights)
// ---------------------------------------------------------------------------
__global__ void wprep_kernel(const float* __restrict__ tw) {
    int i = blockIdx.x * blockDim.x + threadIdx.x;
    if (i >= CIN * KTOT) return;
    {   // deform split
        int o = i / KTOT, kidx = i % KTOT;
        int kk = kidx >> 7, ci = kidx & 127;
        float w = tw[(o * COUT + ci) * KK + kk];
        __nv_bfloat16 h = __float2bfloat16(w);
        g_Whi[i] = h;
        g_Wlo[i] = __float2bfloat16(w - __bfloat162float(h));
    }
    {   // tconv class weights
        int co = i / 2304, kf = i % 2304;
        int cls = (kf >= 1280) ? 3 : (kf >= 768) ? 2 : (kf >= 256) ? 1 : 0;
        int k = kf - c_clsBase[cls];
        int py = cls >> 1, pxp = cls & 1;
        int nkx = pxp ? 2 : 1;
        int tap = k >> 8, ci = k & 255;
        int a = tap / nkx, b = tap % nkx;
        int ky = py ? (a ? 2 : 0) : 1;
        int kx = pxp ? (b ? 2 : 0) : 1;
        float w = tw[(ci * COUT + co) * KK + (2 - ky) * 3 + (2 - kx)];
        __nv_bfloat16 h = __float2bfloat16(w);
        g_Wch[i] = h;
        g_Wcl[i] = __float2bfloat16(w - __bfloat162float(h));
    }
}

// ---------------------------------------------------------------------------
// Kernel 2: x -> channel-last bf16 hi/lo with zero pad row/col 64.
// ---------------------------------------------------------------------------
__global__ void __launch_bounds__(256)
xsplit_kernel(const float* __restrict__ x) {
    const int y0 = blockIdx.x, n = blockIdx.y;
    const int tid = threadIdx.x;
    __nv_bfloat16* oh = g_xpad_hi + (size_t)(n * XP + y0) * XP * CIN;
    __nv_bfloat16* ol = g_xpad_lo + (size_t)(n * XP + y0) * XP * CIN;

    if (y0 == 64) {
        for (int idx = tid; idx < XP * CIN / 8; idx += 256) {
            *(uint4*)(oh + idx * 8) = make_uint4(0, 0, 0, 0);
            *(uint4*)(ol + idx * 8) = make_uint4(0, 0, 0, 0);
        }
        return;
    }
    __shared__ float tile[64][65];
    for (int cc = 0; cc < 4; cc++) {
        #pragma unroll
        for (int r = 0; r < 16; r++) {
            int ci = (tid >> 6) + r * 4;
            int x0 = tid & 63;
            tile[ci][x0] = x[((size_t)(n * CIN + cc * 64 + ci) * HIN + y0) * WIN + x0];
        }
        __syncthreads();
        #pragma unroll
        for (int r = 0; r < 16; r++) {
            int x0 = (tid >> 6) + r * 4;
            int ci = tid & 63;
            float v = tile[ci][x0];
            __nv_bfloat16 h = __float2bfloat16(v);
            oh[x0 * CIN + cc * 64 + ci] = h;
            ol[x0 * CIN + cc * 64 + ci] = __float2bfloat16(v - __bfloat162float(h));
        }
        __syncthreads();
    }
    if (tid < CIN) {
        oh[64 * CIN + tid] = __float2bfloat16(0.f);
        ol[64 * CIN + tid] = __float2bfloat16(0.f);
    }
}

// ---------------------------------------------------------------------------
// Kernel 3: offset branch, warp-parallel
// ---------------------------------------------------------------------------
__global__ void __launch_bounds__(1024)
offsets_kernel(const float* __restrict__ lat,
               const float* __restrict__ w1,
               const float* __restrict__ b1,
               const float* __restrict__ w2,
               const float* __restrict__ b2) {
    __shared__ float h[NB][64];
    __shared__ float oc[NB][18];
    const int tid = threadIdx.x, lane = tid & 31, w = tid >> 5;

    #pragma unroll
    for (int t = 0; t < 4; t++) {
        int o = w * 4 + t;
        int n = o >> 6, j = o & 63;
        float s = 0.f;
        #pragma unroll
        for (int r = 0; r < 4; r++) {
            int i = lane + r * 32;
            s += lat[n * COUT + i] * w1[(j * COUT + i) * KK + 4];
        }
        #pragma unroll
        for (int d = 16; d; d >>= 1) s += __shfl_xor_sync(0xffffffffu, s, d);
        if (lane == 0) h[n][j] = fmaxf(s + b1[j], 0.f);
    }
    __syncthreads();

    for (int o = w; o < NB * 18; o += 32) {
        int n = o / 18, c = o % 18;
        float s = 0.f;
        #pragma unroll
        for (int r = 0; r < 2; r++) {
            int k = lane + r * 32;
            s += h[n][k] * w2[(c * 64 + k) * KK + 4];
        }
        #pragma unroll
        for (int d = 16; d; d >>= 1) s += __shfl_xor_sync(0xffffffffu, s, d);
        if (lane == 0) oc[n][c] = tanhf(s + b2[c]);
    }
    __syncthreads();

    if (tid < NB * KK) {
        int n = tid / KK, kk = tid % KK;
        float oy = oc[n][2 * kk], ox = oc[n][2 * kk + 1];
        float fy = floorf(oy), fx = floorf(ox);
        float dy = oy - fy,  dx = ox - fx;
        g_sy[n][kk] = (kk / 3 - 1) + (int)fy;
        g_sx[n][kk] = (kk % 3 - 1) + (int)fx;
        g_cw[n][kk][0] = (1.f - dy) * (1.f - dx);
        g_cw[n][kk][1] = (1.f - dy) * dx;
        g_cw[n][kk][2] = dy * (1.f - dx);
        g_cw[n][kk][3] = dy * dx;
    }
}

// ---------------------------------------------------------------------------
// Kernel 4: transposed conv as per-parity-class HMMA GEMM (R13 version).
// ---------------------------------------------------------------------------
__global__ void __launch_bounds__(256, 2)
tconv_gemm_kernel() {
    extern __shared__ __align__(16) unsigned char smraw[];
    const int Y   = blockIdx.x;
    const int pxp = blockIdx.y;
    const int n   = blockIdx.z;
    const int tid = threadIdx.x;
    const int lane = tid & 31, warp = tid >> 5;
    const int wm = warp & 1, wn = warp >> 1;

    const int py  = Y & 1;
    const int cls = py * 2 + pxp;
    const int Kc  = c_clsK[cls];
    const int kbase = c_clsBase[cls];
    const int nkx = pxp ? 2 : 1;
    const int stages = Kc >> 5;
    const int y0b = Y >> 1;
    const uint32_t smb = s2u(smraw);

    const __nv_bfloat16* Ah_src = g_Wch;
    const __nv_bfloat16* Al_src = g_Wcl;
    const __nv_bfloat16* Bh_src = g_xpad_hi + (size_t)n * XP * XP * CIN;
    const __nv_bfloat16* Bl_src = g_xpad_lo + (size_t)n * XP * XP * CIN;

    float acc[4][2][4];
    #pragma unroll
    for (int i = 0; i < 4; i++)
        #pragma unroll
        for (int j = 0; j < 2; j++)
            #pragma unroll
            for (int e = 0; e < 4; e++) acc[i][j][e] = 0.f;

    auto issue = [&](int s, int buf) {
        const int k0 = s * 32;
        const int tap = k0 >> 8;
        const int a = tap / nkx, b = tap % nkx;
        const int yy = y0b + (py ? a : 0);
        const int d  = pxp ? b : 0;
        const int cib = k0 & 255;
        const size_t brow = ((size_t)yy * XP) * CIN;
        #pragma unroll
        for (int j = 0; j < 6; j++) {
            int id = tid + j * 256;
            uint32_t base = smb + buf * 30720;
            if (id < 1024) {
                int t = id >> 9;
                int rid = id & 511;
                int r = rid >> 2, c = rid & 3;
                uint32_t dst = base + t * 10240 + r * 80 + c * 16;
                const __nv_bfloat16* src = (t ? Al_src : Ah_src)
                    + (size_t)r * 2304 + kbase + k0 + c * 8;
                cp16(dst, src);
            } else {
                int rid = id - 1024;
                int t = rid >> 8;
                int rr = rid & 255;
                int r = rr >> 2, c = rr & 3;
                uint32_t dst = base + 20480 + t * 5120 + r * 80 + c * 16;
                const __nv_bfloat16* src = (t ? Bl_src : Bh_src)
                    + brow + (size_t)(r + d) * CIN + cib + c * 8;
                cp16(dst, src);
            }
        }
        cp_commit();
    };

    issue(0, 0);

    for (int s = 0; s < stages; s++) {
        cp_wait_all();
        __syncthreads();
        if (s + 1 < stages) issue(s + 1, (s + 1) & 1);

        const int buf = s & 1;
        const uint32_t Ab = smb + buf * 30720;
        const uint32_t Bb = Ab + 20480;

        #pragma unroll
        for (int ks = 0; ks < 2; ks++) {
            uint32_t afr[2][4][4];
            #pragma unroll
            for (int t = 0; t < 2; t++)
                #pragma unroll
                for (int mt = 0; mt < 4; mt++) {
                    uint32_t ad = Ab + t * 10240 +
                        (wm * 64 + mt * 16 + (lane & 15)) * 80 + ks * 32 + (lane >> 4) * 16;
                    ldsm4(afr[t][mt], ad);
                }
            uint32_t bfr[2][2][2];
            #pragma unroll
            for (int t = 0; t < 2; t++)
                #pragma unroll
                for (int nt = 0; nt < 2; nt++) {
                    uint32_t bd = Bb + t * 5120 +
                        (wn * 16 + nt * 8 + (lane & 7)) * 80 + ks * 32 + ((lane >> 3) & 1) * 16;
                    ldsm2(bfr[t][nt], bd);
                }
            #pragma unroll
            for (int mt = 0; mt < 4; mt++)
                #pragma unroll
                for (int nt = 0; nt < 2; nt++) {
                    mma_bf16(acc[mt][nt], afr[0][mt], bfr[0][nt]);
                    mma_bf16(acc[mt][nt], afr[0][mt], bfr[1][nt]);
                    mma_bf16(acc[mt][nt], afr[1][mt], bfr[0][nt]);
                }
        }
        __syncthreads();
    }

    float* up = g_upcl + (size_t)(n * HH + Y) * WW * COUT;
    #pragma unroll
    for (int mt = 0; mt < 4; mt++) {
        int m0 = wm * 64 + mt * 16 + (lane >> 2);
        #pragma unroll
        for (int nt = 0; nt < 2; nt++) {
            int px0 = wn * 16 + nt * 8 + (lane & 3) * 2;
            up[(size_t)(2 * px0 + pxp) * COUT + m0]           = acc[mt][nt][0];
            up[(size_t)(2 * (px0 + 1) + pxp) * COUT + m0]     = acc[mt][nt][1];
            up[(size_t)(2 * px0 + pxp) * COUT + m0 + 8]       = acc[mt][nt][2];
            up[(size_t)(2 * (px0 + 1) + pxp) * COUT + m0 + 8] = acc[mt][nt][3];
        }
    }
}

// ---------------------------------------------------------------------------
// Kernel 5: FUSED deform GEMM (sampler folded in via smem slab staging).
// Grid (y=128, n=2). CTA: M=256 x N=128, 16 warps, 2-buffer ring.
// Per-buffer layout: Ah[0,20480) Al[20480,40960) Bh[40960,51200)
//                    Bl[51200,61440) slab[61440,98880)
// slab: 2 rows x 130 px x 32ci fp32, px stride 144B.
// ---------------------------------------------------------------------------
__global__ void __launch_bounds__(512, 1)
gemm_kernel(float* __restrict__ out) {
    extern __shared__ __align__(16) unsigned char smraw[];
    const int y   = blockIdx.x;
    const int n   = blockIdx.y;
    const int tid = threadIdx.x;
    const int lane = tid & 31, warp = tid >> 5;
    const int wm = warp & 3, wn = warp >> 2;   // 4x4 warp grid: 64 M x 32 N each

    const uint32_t smb = s2u(smraw);

    __shared__ int   ssy[KK], ssx[KK];
    __shared__ float scw[KK][4];
    if (tid < KK) { ssy[tid] = g_sy[n][tid]; ssx[tid] = g_sx[n][tid]; }
    if (tid < KK * 4) ((float*)scw)[tid] = ((const float*)g_cw[n])[tid];
    __syncthreads();

    const __nv_bfloat16* srcA_h = g_Whi;
    const __nv_bfloat16* srcA_l = g_Wlo;
    const float* up_n = g_upcl + (size_t)n * HH * WW * COUT;

    float acc[4][4][4];
    #pragma unroll
    for (int i = 0; i < 4; i++)
        #pragma unroll
        for (int j = 0; j < 4; j++)
            #pragma unroll
            for (int e = 0; e < 4; e++) acc[i][j][e] = 0.f;

    // Per stage: A (2048 cp16) + slab (2080 cp16) = 4128 chunks / 512 thr.
    auto issue = [&](int s, int buf) {
        const int k0 = s * 32;
        const int kk = s >> 2;
        const int cbase = (s & 3) * 32;
        const int sy = ssy[kk], sx = ssx[kk];
        const int ybase = y + sy;
        const uint32_t base = smb + buf * GBUF;
        #pragma unroll
        for (int j = 0; j < 9; j++) {
            int chunk = tid + j * 512;
            if (chunk >= 4128) break;
            if (chunk < 2048) {                 // A tiles: 2 x 256 rows x 4 chunks
                int t = chunk >> 10;
                int rid = chunk & 1023;
                int r = rid >> 2, c = rid & 3;
                uint32_t dst = base + t * 20480 + r * 80 + c * 16;
                const __nv_bfloat16* src = (t ? srcA_l : srcA_h) + (size_t)r * KTOT + k0 + c * 8;
                cp16(dst, src);
            } else {                            // slab: 2 rows x 130 px x 8 chunks
                int id2 = chunk - 2048;         // 0..2079
                int r = (id2 >= 1040) ? 1 : 0;
                int rem = id2 - r * 1040;
                int p = rem >> 3, c = rem & 7;
                int yy = ybase + r;
                int xx = sx + p;
                uint32_t ok = (((unsigned)yy < HH) & ((unsigned)xx < WW)) ? 16u : 0u;
                int yyc = min(max(yy, 0), HH - 1);
                int xc  = min(max(xx, 0), WW - 1);
                const float* src = up_n + ((size_t)yyc * WW + xc) * COUT + cbase + c * 4;
                uint32_t dst = base + SLABO + r * SLABR + p * 144 + c * 16;
                cp16z(dst, src, ok);
            }
        }
        cp_commit();
    };

    issue(0, 0);
    issue(1, 1);

    const int b_px = tid & 127;          // blend mapping
    const int b_g  = tid >> 7;           // 0..3: k-subgroup of 8

    for (int s = 0; s < STAGES; s++) {
        const int buf = s & 1;
        if (s >= STAGES - 2) cp_wait_all(); else cp_wait_1();
        __syncthreads();                 // copies visible; prior MMA(s-1) done

        // ---- blend slab -> bf16 hi/lo B tiles ----
        {
            const int kk = s >> 2;
            const float c00 = scw[kk][0], c01 = scw[kk][1];
            const float c10 = scw[kk][2], c11 = scw[kk][3];
            unsigned char* bb = smraw + buf * GBUF;
            const unsigned char* slab = bb + SLABO;
            const unsigned char* p00 = slab + b_px * 144 + b_g * 32;
            float4 a00 = *(const float4*)(p00);
            float4 b00 = *(const float4*)(p00 + 16);
            float4 a01 = *(const float4*)(p00 + 144);
            float4 b01 = *(const float4*)(p00 + 144 + 16);
            float4 a10 = *(const float4*)(p00 + SLABR);
            float4 b10 = *(const float4*)(p00 + SLABR + 16);
            float4 a11 = *(const float4*)(p00 + SLABR + 144);
            float4 b11 = *(const float4*)(p00 + SLABR + 144 + 16);
            float v[8];
            v[0] = c00 * a00.x + c01 * a01.x + c10 * a10.x + c11 * a11.x;
            v[1] = c00 * a00.y + c01 * a01.y + c10 * a10.y + c11 * a11.y;
            v[2] = c00 * a00.z + c01 * a01.z + c10 * a10.z + c11 * a11.z;
            v[3] = c00 * a00.w + c01 * a01.w + c10 * a10.w + c11 * a11.w;
            v[4] = c00 * b00.x + c01 * b01.x + c10 * b10.x + c11 * b11.x;
            v[5] = c00 * b00.y + c01 * b01.y + c10 * b10.y + c11 * b11.y;
            v[6] = c00 * b00.z + c01 * b01.z + c10 * b10.z + c11 * b11.z;
            v[7] = c00 * b00.w + c01 * b01.w + c10 * b10.w + c11 * b11.w;
            BF8 hi, lo;
            #pragma unroll
            for (int e = 0; e < 8; e++) {
                __nv_bfloat16 hb = __float2bfloat16(v[e]);
                hi.b[e] = hb;
                lo.b[e] = __float2bfloat16(v[e] - __bfloat162float(hb));
            }
            *(uint4*)(bb + 40960 + b_px * 80 + b_g * 16) = hi.v;
            *(uint4*)(bb + 51200 + b_px * 80 + b_g * 16) = lo.v;
        }
        __syncthreads();                 // B tiles ready

        const uint32_t Ab = smb + buf * GBUF;
        const uint32_t Bb = Ab + 40960;

        #pragma unroll
        for (int ks = 0; ks < 2; ks++) {
            uint32_t afr[2][4][4];
            #pragma unroll
            for (int t = 0; t < 2; t++)
                #pragma unroll
                for (int mt = 0; mt < 4; mt++) {
                    uint32_t ad = Ab + t * 20480 +
                        (wm * 64 + mt * 16 + (lane & 15)) * 80 + ks * 32 + (lane >> 4) * 16;
                    ldsm4(afr[t][mt], ad);
                }
            uint32_t bfr[2][4][2];
            #pragma unroll
            for (int t = 0; t < 2; t++)
                #pragma unroll
                for (int nt = 0; nt < 4; nt++) {
                    uint32_t bd = Bb + t * 10240 +
                        (wn * 32 + nt * 8 + (lane & 7)) * 80 + ks * 32 + ((lane >> 3) & 1) * 16;
                    ldsm2(bfr[t][nt], bd);
                }
            #pragma unroll
            for (int mt = 0; mt < 4; mt++)
                #pragma unroll
                for (int nt = 0; nt < 4; nt++) {
                    mma_bf16(acc[mt][nt], afr[0][mt], bfr[0][nt]);
                    mma_bf16(acc[mt][nt], afr[0][mt], bfr[1][nt]);
                    mma_bf16(acc[mt][nt], afr[1][mt], bfr[0][nt]);
                }
        }
        __syncthreads();                 // all warps done with A(buf)+slab(buf)
        if (s + 2 < STAGES) issue(s + 2, buf);
    }

    #pragma unroll
    for (int mt = 0; mt < 4; mt++) {
        int m = wm * 64 + mt * 16 + (lane >> 2);
        float* pbase = out + (((size_t)(n * CIN + m) * HH + y) * WW);
        #pragma unroll
        for (int nt = 0; nt < 4; nt++) {
            int xcol = wn * 32 + nt * 8 + (lane & 3) * 2;
            *(float2*)(pbase + xcol) = make_float2(acc[mt][nt][0], acc[mt][nt][1]);
            *(float2*)(pbase + 8 * HH * WW + xcol) = make_float2(acc[mt][nt][2], acc[mt][nt][3]);
        }
    }
}

// ---------------------------------------------------------------------------
extern "C" void kernel_launch(void* const* d_in, const int* in_sizes, int n_in,
                              void* d_out, int out_size) {
    const float* x   = (const float*)d_in[0];
    const float* lat = (const float*)d_in[1];
    const float* tw  = (const float*)d_in[2];
    const float* w1  = (const float*)d_in[3];
    const float* b1  = (const float*)d_in[4];
    const float* w2  = (const float*)d_in[5];
    const float* b2  = (const float*)d_in[6];
    float* out = (float*)d_out;

    cudaFuncSetAttribute(gemm_kernel,
                         cudaFuncAttributeMaxDynamicSharedMemorySize, 2 * GBUF);
    cudaFuncSetAttribute(tconv_gemm_kernel,
                         cudaFuncAttributeMaxDynamicSharedMemorySize, 61440);

    wprep_kernel<<<(CIN * KTOT + 255) / 256, 256>>>(tw);
    xsplit_kernel<<<dim3(XP, NB), 256>>>(x);
    offsets_kernel<<<1, 1024>>>(lat, w1, b1, w2, b2);
    {
        dim3 grid(HH, 2, NB);
        tconv_gemm_kernel<<<grid, 256, 61440>>>();
    }
    {
        dim3 grid(HH, NB);
        gemm_kernel<<<grid, 512, 2 * GBUF>>>(out);
    }
}